// round 13
// baseline (speedup 1.0000x reference)
#include <cuda_runtime.h>
#include <cstdint>

// Problem dims
#define B_  256
#define T_  64
#define K_  49
#define H_  512
#define A_  49
#define BT  (B_ * T_)            // 16384
#define BK  (B_ * K_)            // 12544
#define BTH ((size_t)BT * H_)    // 8388608
#define BTK ((size_t)BT * K_)    // 802816
#define CP  52                   // padded row pitch for scratch [*, 52]

// Scratch (device globals; no allocations allowed)
__device__ __align__(16) float    g_cv[B_ * K_ * CP];   // content_v  [b,k,52]
__device__ __align__(16) float    g_cg[B_ * T_ * CP];   // content_g  [b,t,52]
__device__ __align__(16) float    g_cs[B_ * T_ * CP];   // s_t@Ws^T   [b,t,52]
__device__ __align__(16) float    g_Wp[3 * 32768];      // permuted W fragments
__device__ __align__(16) uint32_t g_ahi[BT * 32];       // alpha hi bf16x2 [bt][kpair]
__device__ __align__(16) uint32_t g_alo[BT * 32];       // alpha lo bf16x2 [bt][kpair]

typedef unsigned long long u64;

__device__ __forceinline__ float tanh_approx(float x) {
    float y;
    asm("tanh.approx.f32 %0, %1;" : "=f"(y) : "f"(x));
    return y;
}
__device__ __forceinline__ u64 pack2(float lo, float hi) {
    u64 d;
    asm("mov.b64 %0, {%1, %2};" : "=l"(d) : "f"(lo), "f"(hi));
    return d;
}
__device__ __forceinline__ uint32_t s2u(const void* p) {
    uint32_t a;
    asm("{ .reg .u64 t; cvta.to.shared.u64 t, %1; cvt.u32.u64 %0, t; }"
        : "=r"(a) : "l"(p));
    return a;
}
__device__ __forceinline__ void cpa16(uint32_t dst, const void* src) {
    asm volatile("cp.async.cg.shared.global [%0], [%1], 16;"
                 :: "r"(dst), "l"(src) : "memory");
}
__device__ __forceinline__ void prefetchL2(const void* p) {
    asm volatile("prefetch.global.L2 [%0];" :: "l"(p));
}
__device__ __forceinline__ void mma_tf32(float* d,
                                         float a0, float a1, float a2, float a3,
                                         float b0, float b1) {
    asm volatile(
        "mma.sync.aligned.m16n8k8.row.col.f32.tf32.tf32.f32 "
        "{%0,%1,%2,%3}, {%4,%5,%6,%7}, {%8,%9}, {%0,%1,%2,%3};"
        : "+f"(d[0]), "+f"(d[1]), "+f"(d[2]), "+f"(d[3])
        : "r"(__float_as_uint(a0)), "r"(__float_as_uint(a1)),
          "r"(__float_as_uint(a2)), "r"(__float_as_uint(a3)),
          "r"(__float_as_uint(b0)), "r"(__float_as_uint(b1)));
}
__device__ __forceinline__ void mma_bf16(float* d,
                                         uint32_t a0, uint32_t a1, uint32_t a2, uint32_t a3,
                                         uint32_t b0, uint32_t b1) {
    asm volatile(
        "mma.sync.aligned.m16n8k16.row.col.f32.bf16.bf16.f32 "
        "{%0,%1,%2,%3}, {%4,%5,%6,%7}, {%8,%9}, {%0,%1,%2,%3};"
        : "+f"(d[0]), "+f"(d[1]), "+f"(d[2]), "+f"(d[3])
        : "r"(a0), "r"(a1), "r"(a2), "r"(a3), "r"(b0), "r"(b1));
}
__device__ __forceinline__ uint32_t bf2pack(float x0, float x1) {
    uint32_t h;
    asm("cvt.rn.bf16x2.f32 %0, %1, %2;" : "=r"(h) : "f"(x1), "f"(x0));
    return h;
}
__device__ __forceinline__ void bf2split(float x0, float x1,
                                         uint32_t& hi, uint32_t& lo) {
    hi = bf2pack(x0, x1);
    float r0 = __uint_as_float(hi << 16);
    float r1 = __uint_as_float(hi & 0xffff0000u);
    lo = bf2pack(x0 - r0, x1 - r1);
}

// ---------------------------------------------------------------------------
// Permute W matrices into mma.sync B-fragment order.
// ---------------------------------------------------------------------------
__global__ __launch_bounds__(128)
void wperm_kernel(const float* __restrict__ Wv, const float* __restrict__ Wg,
                  const float* __restrict__ Ws_)
{
    int tid = blockIdx.x * 128 + threadIdx.x;       // 0..24575
    int mat = tid / 8192;
    int rem = tid % 8192;
    int S   = rem / 128;
    int j   = (rem / 32) % 4;
    int l   = rem % 32;
    int g = l >> 2, tg = l & 3;
    int k = S * 8 + tg;
    int r0 = 16 * j + g, r1 = r0 + 8;
    const float* W = (mat == 0) ? Wv : (mat == 1) ? Wg : Ws_;
    float4 F;
    F.x = (r0 < A_) ? W[(size_t)r0 * H_ + k]     : 0.f;
    F.y = (r0 < A_) ? W[(size_t)r0 * H_ + k + 4] : 0.f;
    F.z = (r1 < A_) ? W[(size_t)r1 * H_ + k]     : 0.f;
    F.w = (r1 < A_) ? W[(size_t)r1 * H_ + k + 4] : 0.f;
    *(float4*)&g_Wp[(size_t)mat * 32768 + (size_t)rem * 4] = F;
}

// ---------------------------------------------------------------------------
// tf32 mma.sync content GEMM, double-buffered K=32 chunks, 6 CTA/SM (1 wave).
// ---------------------------------------------------------------------------
#define XPW 36     // X smem pitch (floats)

__global__ __launch_bounds__(128, 6)
void gemm_mma_kernel(const float* __restrict__ V,   const float* __restrict__ h_t,
                     const float* __restrict__ s_t)
{
    __shared__ __align__(16) float Xs[2][64][XPW];
    __shared__ __align__(16) float Bs[2][2048];

    const float* X; const float* wp; float* out; int row0;
    const int bid = blockIdx.x;
    if (bid < 196)      { X = V;   wp = g_Wp;          out = g_cv; row0 = bid * 64; }
    else if (bid < 452) { X = h_t; wp = g_Wp + 32768;  out = g_cg; row0 = (bid - 196) * 64; }
    else                { X = s_t; wp = g_Wp + 65536;  out = g_cs; row0 = (bid - 452) * 64; }

    const int tid  = threadIdx.x;
    const int wid  = tid >> 5;
    const int lane = tid & 31;
    const int g    = lane >> 2;
    const int tg   = lane & 3;
    const uint32_t xs_u[2] = { s2u(&Xs[0][0][0]), s2u(&Xs[1][0][0]) };
    const uint32_t bs_u[2] = { s2u(&Bs[0][0]),    s2u(&Bs[1][0]) };

    auto load_chunk = [&](int c) {
        const int p = c & 1;
        #pragma unroll
        for (int i = 0; i < 4; i++) {
            int idx = tid + i * 128;
            int r = idx >> 3, c4 = idx & 7;
            cpa16(xs_u[p] + (uint32_t)(r * XPW + c4 * 4) * 4,
                  &X[(size_t)(row0 + r) * H_ + c * 32 + c4 * 4]);
        }
        #pragma unroll
        for (int i = 0; i < 4; i++) {
            int idx = tid + i * 128;
            cpa16(bs_u[p] + (uint32_t)idx * 16, wp + (size_t)c * 2048 + (size_t)idx * 4);
        }
        asm volatile("cp.async.commit_group;" ::: "memory");
    };

    float acc[8][4];
    #pragma unroll
    for (int n = 0; n < 8; n++)
        #pragma unroll
        for (int c = 0; c < 4; c++) acc[n][c] = 0.f;

    load_chunk(0);
    for (int c = 0; c < 16; c++) {
        if (c + 1 < 16) {
            load_chunk(c + 1);
            asm volatile("cp.async.wait_group 1;" ::: "memory");
        } else {
            asm volatile("cp.async.wait_group 0;" ::: "memory");
        }
        __syncthreads();

        const int p = c & 1;
        #pragma unroll
        for (int s = 0; s < 4; s++) {
            float a0 = Xs[p][16*wid + g    ][s*8 + tg    ];
            float a1 = Xs[p][16*wid + g + 8][s*8 + tg    ];
            float a2 = Xs[p][16*wid + g    ][s*8 + tg + 4];
            float a3 = Xs[p][16*wid + g + 8][s*8 + tg + 4];
            #pragma unroll
            for (int j = 0; j < 4; j++) {
                float4 bf = *(const float4*)&Bs[p][((s*4 + j) * 32 + lane) * 4];
                mma_tf32(acc[2*j],     a0, a1, a2, a3, bf.x, bf.y);
                mma_tf32(acc[2*j + 1], a0, a1, a2, a3, bf.z, bf.w);
            }
        }
        __syncthreads();
    }

    const int r0g = row0 + 16 * wid + g;
    #pragma unroll
    for (int n = 0; n < 8; n++) {
        int col0 = n * 8 + tg * 2;
        if (col0 < CP) {
            *(u64*)&out[(size_t)r0g * CP + col0]       = pack2(acc[n][0], acc[n][1]);
            *(u64*)&out[(size_t)(r0g + 8) * CP + col0] = pack2(acc[n][2], acc[n][3]);
        }
    }
}

// ---------------------------------------------------------------------------
// zsoft: z_t + z_ext + softmax(alpha) + extended softmax(beta).
// Also emits pre-split bf16 hi/lo alpha tiles (g_ahi/g_alo) for chat.
// ---------------------------------------------------------------------------
#define TZ 16
#define ZP 52

__global__ __launch_bounds__(256)
void zsoft_kernel(const float* __restrict__ Wh,
                  float* __restrict__ out_alpha, float* __restrict__ out_beta)
{
    const int b  = blockIdx.y;
    const int t0 = blockIdx.x * TZ;
    __shared__ __align__(16) float cvs[K_ * ZP];
    __shared__ __align__(16) float cgs[TZ * ZP];
    __shared__ __align__(16) float css[TZ * ZP];
    __shared__ __align__(16) float whs[52];
    __shared__ float zes[TZ];
    __shared__ float zs[TZ * 50];
    const int tid = threadIdx.x;

    for (int i = tid; i < K_ * 13; i += 256) {
        int k = i / 13, c4 = i % 13;
        *(float4*)&cvs[k * ZP + c4*4] =
            *(const float4*)&g_cv[((size_t)b * K_ + k) * CP + c4*4];
    }
    for (int i = tid; i < TZ * 13; i += 256) {
        int t = i / 13, c4 = i % 13;
        size_t src = ((size_t)b * T_ + t0 + t) * CP + c4*4;
        *(float4*)&cgs[t * ZP + c4*4] = *(const float4*)&g_cg[src];
        *(float4*)&css[t * ZP + c4*4] = *(const float4*)&g_cs[src];
    }
    if (tid < 52) whs[tid] = (tid < A_) ? Wh[tid] : 0.f;
    __syncthreads();

    for (int item = tid; item < TZ * K_ + TZ; item += 256) {
        const float* rowA;
        const float* rowB;
        if (item < TZ * K_) {
            int t = item / K_, k = item % K_;
            rowA = &cgs[t * ZP];
            rowB = &cvs[k * ZP];
        } else {
            int t = item - TZ * K_;
            rowA = &cgs[t * ZP];
            rowB = &css[t * ZP];
        }
        float s0 = 0.f, s1 = 0.f, s2 = 0.f, s3 = 0.f;
        #pragma unroll
        for (int a = 0; a < 48; a += 4) {
            float4 A = *(const float4*)&rowA[a];
            float4 Bv = *(const float4*)&rowB[a];
            float4 W = *(const float4*)&whs[a];
            s0 = fmaf(tanh_approx(A.x + Bv.x), W.x, s0);
            s1 = fmaf(tanh_approx(A.y + Bv.y), W.y, s1);
            s2 = fmaf(tanh_approx(A.z + Bv.z), W.z, s2);
            s3 = fmaf(tanh_approx(A.w + Bv.w), W.w, s3);
        }
        s0 = fmaf(tanh_approx(rowA[48] + rowB[48]), whs[48], s0);
        float z = (s0 + s1) + (s2 + s3);
        if (item < TZ * K_) {
            int t = item / K_, k = item % K_;
            zs[t * 50 + k] = z;
        } else {
            zes[item - TZ * K_] = z;
        }
    }
    __syncthreads();

    const int warp = tid >> 5, lane = tid & 31;
    for (int t = warp; t < TZ; t += 8) {
        float z1 = (lane < K_)      ? zs[t*50 + lane]      : -1e30f;
        float z2 = (lane + 32 < K_) ? zs[t*50 + lane + 32] : -1e30f;
        float m = fmaxf(z1, z2);
        #pragma unroll
        for (int o = 16; o; o >>= 1) m = fmaxf(m, __shfl_xor_sync(0xffffffffu, m, o));
        float e1 = (lane < K_)      ? __expf(z1 - m) : 0.f;
        float e2 = (lane + 32 < K_) ? __expf(z2 - m) : 0.f;
        float s = e1 + e2;
        #pragma unroll
        for (int o = 16; o; o >>= 1) s += __shfl_xor_sync(0xffffffffu, s, o);
        float inv = 1.f / s;
        size_t bt = (size_t)b * T_ + t0 + t;
        float a1v = e1 * inv, a2v = e2 * inv;
        if (lane < K_) {
            out_alpha[bt * K_ + lane] = a1v;
            zs[t*50 + lane] = a1v;                 // overwrite z with alpha
        }
        if (lane + 32 < K_) {
            out_alpha[bt * K_ + lane + 32] = a2v;
            zs[t*50 + lane + 32] = a2v;
        }
        if (lane == 0) {
            float ze = zes[t];
            float m2 = fmaxf(m, ze);
            float ee = __expf(ze - m2);
            float denom = s * __expf(m - m2) + ee;
            out_beta[bt] = ee / denom;
        }
    }
    __syncthreads();

    // Emit pre-split bf16 alpha tiles: [bt][32 kpairs], kpairs >= 25 zero.
    for (int item = tid; item < TZ * 32; item += 256) {
        int t = item >> 5, kp = item & 31;
        float x0 = (2*kp     < K_) ? zs[t*50 + 2*kp]     : 0.f;
        float x1 = (2*kp + 1 < K_) ? zs[t*50 + 2*kp + 1] : 0.f;
        uint32_t h, l;
        bf2split(x0, x1, h, l);
        size_t dst = ((size_t)b * T_ + t0 + t) * 32 + kp;
        g_ahi[dst] = h;
        g_alo[dst] = l;
    }
}

// ---------------------------------------------------------------------------
// chat via 2-term bf16-split m16n8k16 mma. Grid (2, B) = 512 blocks (<=0.86
// waves at 4 CTA/SM); each block walks TWO 128-wide h-chunks reusing the
// alpha hi/lo tiles (loaded once via cp.async from zsoft's pre-split output).
// ---------------------------------------------------------------------------
#define VPU 136            // u32 pitch of V hi/lo tiles [32 kpairs][128 n]
#define APU 36             // u32 pitch of A hi/lo tiles [64 t][32 kpairs]
#define V_U32 (32 * VPU)   // 4352
#define A_U32 (64 * APU)   // 2304
#define SMEM_CHAT ((2 * V_U32 + 2 * A_U32 + 64) * 4)   // 53504 bytes

__global__ __launch_bounds__(256)
void chat_mma_kernel(const float* __restrict__ V, const float* __restrict__ s_t,
                     const float* __restrict__ beta, float* __restrict__ out)
{
    extern __shared__ __align__(16) uint32_t csm[];
    uint32_t* Vhi = csm;
    uint32_t* Vlo = csm + V_U32;
    uint32_t* Ahi = csm + 2 * V_U32;
    uint32_t* Alo = csm + 2 * V_U32 + A_U32;
    float*    bsm = (float*)(csm + 2 * V_U32 + 2 * A_U32);

    const int b   = blockIdx.y;
    const int hc0 = blockIdx.x * 256;    // this block's 256-wide h range
    const int tid = threadIdx.x;
    const uint32_t ahi_u = s2u(Ahi);
    const uint32_t alo_u = s2u(Alo);

    // Prefetch the epilogue's s_t working set (both chunks) into L2.
    {
        int t = tid >> 2, ln = tid & 3;
        prefetchL2(&s_t[((size_t)b * T_ + t) * H_ + hc0 + ln * 64]);
    }

    // Alpha hi/lo tiles via cp.async: 64 rows x 8 16B-chunks each (once).
    #pragma unroll
    for (int i = 0; i < 2; i++) {
        int idx = tid + i * 256;
        int row = idx >> 3, c4 = idx & 7;
        cpa16(ahi_u + (uint32_t)(row * APU + c4 * 4) * 4,
              &g_ahi[((size_t)b * T_ + row) * 32 + c4 * 4]);
        cpa16(alo_u + (uint32_t)(row * APU + c4 * 4) * 4,
              &g_alo[((size_t)b * T_ + row) * 32 + c4 * 4]);
    }
    asm volatile("cp.async.commit_group;" ::: "memory");
    if (tid < T_) bsm[tid] = beta[(size_t)b * T_ + tid];

    const int wid  = tid >> 5;
    const int lane = tid & 31;
    const int g    = lane >> 2;
    const int tg   = lane & 3;
    const int mw   = wid & 3;
    const int nh   = wid >> 2;
    const int row  = 16 * mw + g;

    // Zero pad kpairs 25..31 of V tiles (constant across chunks).
    for (int idx = tid; idx < 2 * 7 * 32; idx += 256) {
        int p = idx / 224, r = idx % 224;
        int kp = 25 + r / 32, n4 = r % 32;
        uint32_t* dst = p ? Vlo : Vhi;
        *(uint4*)&dst[kp * VPU + n4 * 4] = make_uint4(0, 0, 0, 0);
    }

    for (int c = 0; c < 2; c++) {
        const int hc = hc0 + c * 128;

        // V tile: 25 kpairs x 32 float4-cols, split to hi/lo.
        for (int idx = tid; idx < 25 * 32; idx += 256) {
            int kp = idx >> 5, n4 = idx & 31;
            const float* p0 = &V[((size_t)b * K_ + 2 * kp) * H_ + hc + n4 * 4];
            float4 x0 = *(const float4*)p0;
            float4 x1 = make_float4(0.f, 0.f, 0.f, 0.f);
            if (2 * kp + 1 < K_) x1 = *(const float4*)(p0 + H_);
            uint4 h, l;
            bf2split(x0.x, x1.x, h.x, l.x);
            bf2split(x0.y, x1.y, h.y, l.y);
            bf2split(x0.z, x1.z, h.z, l.z);
            bf2split(x0.w, x1.w, h.w, l.w);
            *(uint4*)&Vhi[kp * VPU + n4 * 4] = h;
            *(uint4*)&Vlo[kp * VPU + n4 * 4] = l;
        }
        if (c == 0) asm volatile("cp.async.wait_group 0;" ::: "memory");
        __syncthreads();

        float acc[8][4];
        #pragma unroll
        for (int j = 0; j < 8; j++)
            #pragma unroll
            for (int q = 0; q < 4; q++) acc[j][q] = 0.f;

        #pragma unroll
        for (int ks = 0; ks < 4; ks++) {
            uint32_t ah0 = Ahi[ row      * APU + ks*8 + tg    ];
            uint32_t ah1 = Ahi[(row + 8) * APU + ks*8 + tg    ];
            uint32_t ah2 = Ahi[ row      * APU + ks*8 + tg + 4];
            uint32_t ah3 = Ahi[(row + 8) * APU + ks*8 + tg + 4];
            uint32_t al0 = Alo[ row      * APU + ks*8 + tg    ];
            uint32_t al1 = Alo[(row + 8) * APU + ks*8 + tg    ];
            uint32_t al2 = Alo[ row      * APU + ks*8 + tg + 4];
            uint32_t al3 = Alo[(row + 8) * APU + ks*8 + tg + 4];
            #pragma unroll
            for (int j = 0; j < 8; j++) {
                int n = nh*64 + j*8 + g;
                uint32_t bh0 = Vhi[(ks*8 + tg    ) * VPU + n];
                uint32_t bh1 = Vhi[(ks*8 + tg + 4) * VPU + n];
                uint32_t bl0 = Vlo[(ks*8 + tg    ) * VPU + n];
                uint32_t bl1 = Vlo[(ks*8 + tg + 4) * VPU + n];
                mma_bf16(acc[j], ah0, ah1, ah2, ah3, bh0, bh1);   // hi*hi
                mma_bf16(acc[j], ah0, ah1, ah2, ah3, bl0, bl1);   // hi*lo
                mma_bf16(acc[j], al0, al1, al2, al3, bh0, bh1);   // lo*hi
            }
        }

        // Blend epilogue (regs + gmem only).
        const float bv0 = bsm[row],     ob0 = 1.f - bv0;
        const float bv1 = bsm[row + 8], ob1 = 1.f - bv1;
        #pragma unroll
        for (int j = 0; j < 8; j++) {
            int col = hc + nh*64 + j*8 + 2*tg;
            size_t base0 = ((size_t)b * T_ + row)     * H_ + col;
            size_t base1 = ((size_t)b * T_ + row + 8) * H_ + col;
            float2 s0 = *(const float2*)&s_t[base0];
            float2 s1 = *(const float2*)&s_t[base1];
            float2 o0, o1;
            o0.x = fmaf(bv0, s0.x, ob0 * acc[j][0]);
            o0.y = fmaf(bv0, s0.y, ob0 * acc[j][1]);
            o1.x = fmaf(bv1, s1.x, ob1 * acc[j][2]);
            o1.y = fmaf(bv1, s1.y, ob1 * acc[j][3]);
            *(float2*)&out[base0] = o0;
            *(float2*)&out[base1] = o1;
        }
        if (c == 0) __syncthreads();   // all warps done reading V tile before refill
    }
}

extern "C" void kernel_launch(void* const* d_in, const int* in_sizes, int n_in,
                              void* d_out, int out_size)
{
    (void)in_sizes; (void)n_in; (void)out_size;
    const float* V   = (const float*)d_in[0];   // (B,K,H)
    const float* h_t = (const float*)d_in[1];   // (B,T,H)
    const float* s_t = (const float*)d_in[2];   // (B,T,H)
    const float* Wv  = (const float*)d_in[3];   // (K,H)
    const float* Wg  = (const float*)d_in[4];   // (K,H)
    const float* Ws_ = (const float*)d_in[5];   // (K,H)
    const float* Wh  = (const float*)d_in[6];   // (1,K)

    float* out       = (float*)d_out;
    float* out_chat  = out;                 // (B,T,H)
    float* out_alpha = out + BTH;           // (B,T,K)
    float* out_beta  = out + BTH + BTK;     // (B,T,1)

    cudaFuncSetAttribute(chat_mma_kernel,
                         cudaFuncAttributeMaxDynamicSharedMemorySize, SMEM_CHAT);

    wperm_kernel<<<192, 128>>>(Wv, Wg, Ws_);
    gemm_mma_kernel<<<708, 128>>>(V, h_t, s_t);
    zsoft_kernel<<<dim3(4, B_), 256>>>(Wh, out_alpha, out_beta);
    chat_mma_kernel<<<dim3(2, B_), 256, SMEM_CHAT>>>(V, s_t, out_beta, out_chat);
}

// round 14
// speedup vs baseline: 1.0764x; 1.0764x over previous
#include <cuda_runtime.h>
#include <cstdint>

// Problem dims
#define B_  256
#define T_  64
#define K_  49
#define H_  512
#define A_  49
#define BT  (B_ * T_)            // 16384
#define BK  (B_ * K_)            // 12544
#define BTH ((size_t)BT * H_)    // 8388608
#define BTK ((size_t)BT * K_)    // 802816
#define CP  52                   // padded row pitch for scratch [*, 52]

typedef unsigned long long u64;

// Scratch (device globals; no allocations allowed)
__device__ __align__(16) float g_cv[B_ * K_ * CP];   // content_v  [b,k,52]
__device__ __align__(16) float g_cg[B_ * T_ * CP];   // content_g  [b,t,52]
__device__ __align__(16) float g_cs[B_ * T_ * CP];   // s_t@Ws^T   [b,t,52]
__device__ __align__(16) float g_Wp[3 * 32768];      // permuted W fragments
__device__ __align__(16) u64   g_ahl[BT * 32];       // alpha (hi,lo) bf16x2 pairs

__device__ __forceinline__ float tanh_approx(float x) {
    float y;
    asm("tanh.approx.f32 %0, %1;" : "=f"(y) : "f"(x));
    return y;
}
__device__ __forceinline__ u64 pack2(float lo, float hi) {
    u64 d;
    asm("mov.b64 %0, {%1, %2};" : "=l"(d) : "f"(lo), "f"(hi));
    return d;
}
__device__ __forceinline__ uint32_t s2u(const void* p) {
    uint32_t a;
    asm("{ .reg .u64 t; cvta.to.shared.u64 t, %1; cvt.u32.u64 %0, t; }"
        : "=r"(a) : "l"(p));
    return a;
}
__device__ __forceinline__ void cpa16(uint32_t dst, const void* src) {
    asm volatile("cp.async.cg.shared.global [%0], [%1], 16;"
                 :: "r"(dst), "l"(src) : "memory");
}
__device__ __forceinline__ void prefetchL2(const void* p) {
    asm volatile("prefetch.global.L2 [%0];" :: "l"(p));
}
__device__ __forceinline__ void mma_tf32(float* d,
                                         float a0, float a1, float a2, float a3,
                                         float b0, float b1) {
    asm volatile(
        "mma.sync.aligned.m16n8k8.row.col.f32.tf32.tf32.f32 "
        "{%0,%1,%2,%3}, {%4,%5,%6,%7}, {%8,%9}, {%0,%1,%2,%3};"
        : "+f"(d[0]), "+f"(d[1]), "+f"(d[2]), "+f"(d[3])
        : "r"(__float_as_uint(a0)), "r"(__float_as_uint(a1)),
          "r"(__float_as_uint(a2)), "r"(__float_as_uint(a3)),
          "r"(__float_as_uint(b0)), "r"(__float_as_uint(b1)));
}
__device__ __forceinline__ void mma_bf16(float* d,
                                         uint32_t a0, uint32_t a1, uint32_t a2, uint32_t a3,
                                         uint32_t b0, uint32_t b1) {
    asm volatile(
        "mma.sync.aligned.m16n8k16.row.col.f32.bf16.bf16.f32 "
        "{%0,%1,%2,%3}, {%4,%5,%6,%7}, {%8,%9}, {%0,%1,%2,%3};"
        : "+f"(d[0]), "+f"(d[1]), "+f"(d[2]), "+f"(d[3])
        : "r"(a0), "r"(a1), "r"(a2), "r"(a3), "r"(b0), "r"(b1));
}
__device__ __forceinline__ uint32_t bf2pack(float x0, float x1) {
    uint32_t h;
    asm("cvt.rn.bf16x2.f32 %0, %1, %2;" : "=r"(h) : "f"(x1), "f"(x0));
    return h;
}
__device__ __forceinline__ void bf2split(float x0, float x1,
                                         uint32_t& hi, uint32_t& lo) {
    hi = bf2pack(x0, x1);
    float r0 = __uint_as_float(hi << 16);
    float r1 = __uint_as_float(hi & 0xffff0000u);
    lo = bf2pack(x0 - r0, x1 - r1);
}

// ---------------------------------------------------------------------------
// Permute W matrices into mma.sync B-fragment order.
// ---------------------------------------------------------------------------
__global__ __launch_bounds__(128)
void wperm_kernel(const float* __restrict__ Wv, const float* __restrict__ Wg,
                  const float* __restrict__ Ws_)
{
    int tid = blockIdx.x * 128 + threadIdx.x;       // 0..24575
    int mat = tid / 8192;
    int rem = tid % 8192;
    int S   = rem / 128;
    int j   = (rem / 32) % 4;
    int l   = rem % 32;
    int g = l >> 2, tg = l & 3;
    int k = S * 8 + tg;
    int r0 = 16 * j + g, r1 = r0 + 8;
    const float* W = (mat == 0) ? Wv : (mat == 1) ? Wg : Ws_;
    float4 F;
    F.x = (r0 < A_) ? W[(size_t)r0 * H_ + k]     : 0.f;
    F.y = (r0 < A_) ? W[(size_t)r0 * H_ + k + 4] : 0.f;
    F.z = (r1 < A_) ? W[(size_t)r1 * H_ + k]     : 0.f;
    F.w = (r1 < A_) ? W[(size_t)r1 * H_ + k + 4] : 0.f;
    *(float4*)&g_Wp[(size_t)mat * 32768 + (size_t)rem * 4] = F;
}

// ---------------------------------------------------------------------------
// tf32 mma.sync content GEMM, double-buffered K=32 chunks, 6 CTA/SM (1 wave).
// ---------------------------------------------------------------------------
#define XPW 36     // X smem pitch (floats)

__global__ __launch_bounds__(128, 6)
void gemm_mma_kernel(const float* __restrict__ V,   const float* __restrict__ h_t,
                     const float* __restrict__ s_t)
{
    __shared__ __align__(16) float Xs[2][64][XPW];
    __shared__ __align__(16) float Bs[2][2048];

    const float* X; const float* wp; float* out; int row0;
    const int bid = blockIdx.x;
    if (bid < 196)      { X = V;   wp = g_Wp;          out = g_cv; row0 = bid * 64; }
    else if (bid < 452) { X = h_t; wp = g_Wp + 32768;  out = g_cg; row0 = (bid - 196) * 64; }
    else                { X = s_t; wp = g_Wp + 65536;  out = g_cs; row0 = (bid - 452) * 64; }

    const int tid  = threadIdx.x;
    const int wid  = tid >> 5;
    const int lane = tid & 31;
    const int g    = lane >> 2;
    const int tg   = lane & 3;
    const uint32_t xs_u[2] = { s2u(&Xs[0][0][0]), s2u(&Xs[1][0][0]) };
    const uint32_t bs_u[2] = { s2u(&Bs[0][0]),    s2u(&Bs[1][0]) };

    auto load_chunk = [&](int c) {
        const int p = c & 1;
        #pragma unroll
        for (int i = 0; i < 4; i++) {
            int idx = tid + i * 128;
            int r = idx >> 3, c4 = idx & 7;
            cpa16(xs_u[p] + (uint32_t)(r * XPW + c4 * 4) * 4,
                  &X[(size_t)(row0 + r) * H_ + c * 32 + c4 * 4]);
        }
        #pragma unroll
        for (int i = 0; i < 4; i++) {
            int idx = tid + i * 128;
            cpa16(bs_u[p] + (uint32_t)idx * 16, wp + (size_t)c * 2048 + (size_t)idx * 4);
        }
        asm volatile("cp.async.commit_group;" ::: "memory");
    };

    float acc[8][4];
    #pragma unroll
    for (int n = 0; n < 8; n++)
        #pragma unroll
        for (int c = 0; c < 4; c++) acc[n][c] = 0.f;

    load_chunk(0);
    for (int c = 0; c < 16; c++) {
        if (c + 1 < 16) {
            load_chunk(c + 1);
            asm volatile("cp.async.wait_group 1;" ::: "memory");
        } else {
            asm volatile("cp.async.wait_group 0;" ::: "memory");
        }
        __syncthreads();

        const int p = c & 1;
        #pragma unroll
        for (int s = 0; s < 4; s++) {
            float a0 = Xs[p][16*wid + g    ][s*8 + tg    ];
            float a1 = Xs[p][16*wid + g + 8][s*8 + tg    ];
            float a2 = Xs[p][16*wid + g    ][s*8 + tg + 4];
            float a3 = Xs[p][16*wid + g + 8][s*8 + tg + 4];
            #pragma unroll
            for (int j = 0; j < 4; j++) {
                float4 bf = *(const float4*)&Bs[p][((s*4 + j) * 32 + lane) * 4];
                mma_tf32(acc[2*j],     a0, a1, a2, a3, bf.x, bf.y);
                mma_tf32(acc[2*j + 1], a0, a1, a2, a3, bf.z, bf.w);
            }
        }
        __syncthreads();
    }

    const int r0g = row0 + 16 * wid + g;
    #pragma unroll
    for (int n = 0; n < 8; n++) {
        int col0 = n * 8 + tg * 2;
        if (col0 < CP) {
            *(u64*)&out[(size_t)r0g * CP + col0]       = pack2(acc[n][0], acc[n][1]);
            *(u64*)&out[(size_t)(r0g + 8) * CP + col0] = pack2(acc[n][2], acc[n][3]);
        }
    }
}

// ---------------------------------------------------------------------------
// zsoft: z_t + z_ext + softmax(alpha) + extended softmax(beta).
// Emits interleaved (hi,lo) bf16x2 alpha pairs (g_ahl) for chat.
// ---------------------------------------------------------------------------
#define TZ 16
#define ZP 52

__global__ __launch_bounds__(256)
void zsoft_kernel(const float* __restrict__ Wh,
                  float* __restrict__ out_alpha, float* __restrict__ out_beta)
{
    const int b  = blockIdx.y;
    const int t0 = blockIdx.x * TZ;
    __shared__ __align__(16) float cvs[K_ * ZP];
    __shared__ __align__(16) float cgs[TZ * ZP];
    __shared__ __align__(16) float css[TZ * ZP];
    __shared__ __align__(16) float whs[52];
    __shared__ float zes[TZ];
    __shared__ float zs[TZ * 50];
    const int tid = threadIdx.x;

    for (int i = tid; i < K_ * 13; i += 256) {
        int k = i / 13, c4 = i % 13;
        *(float4*)&cvs[k * ZP + c4*4] =
            *(const float4*)&g_cv[((size_t)b * K_ + k) * CP + c4*4];
    }
    for (int i = tid; i < TZ * 13; i += 256) {
        int t = i / 13, c4 = i % 13;
        size_t src = ((size_t)b * T_ + t0 + t) * CP + c4*4;
        *(float4*)&cgs[t * ZP + c4*4] = *(const float4*)&g_cg[src];
        *(float4*)&css[t * ZP + c4*4] = *(const float4*)&g_cs[src];
    }
    if (tid < 52) whs[tid] = (tid < A_) ? Wh[tid] : 0.f;
    __syncthreads();

    for (int item = tid; item < TZ * K_ + TZ; item += 256) {
        const float* rowA;
        const float* rowB;
        if (item < TZ * K_) {
            int t = item / K_, k = item % K_;
            rowA = &cgs[t * ZP];
            rowB = &cvs[k * ZP];
        } else {
            int t = item - TZ * K_;
            rowA = &cgs[t * ZP];
            rowB = &css[t * ZP];
        }
        float s0 = 0.f, s1 = 0.f, s2 = 0.f, s3 = 0.f;
        #pragma unroll
        for (int a = 0; a < 48; a += 4) {
            float4 A = *(const float4*)&rowA[a];
            float4 Bv = *(const float4*)&rowB[a];
            float4 W = *(const float4*)&whs[a];
            s0 = fmaf(tanh_approx(A.x + Bv.x), W.x, s0);
            s1 = fmaf(tanh_approx(A.y + Bv.y), W.y, s1);
            s2 = fmaf(tanh_approx(A.z + Bv.z), W.z, s2);
            s3 = fmaf(tanh_approx(A.w + Bv.w), W.w, s3);
        }
        s0 = fmaf(tanh_approx(rowA[48] + rowB[48]), whs[48], s0);
        float z = (s0 + s1) + (s2 + s3);
        if (item < TZ * K_) {
            int t = item / K_, k = item % K_;
            zs[t * 50 + k] = z;
        } else {
            zes[item - TZ * K_] = z;
        }
    }
    __syncthreads();

    const int warp = tid >> 5, lane = tid & 31;
    for (int t = warp; t < TZ; t += 8) {
        float z1 = (lane < K_)      ? zs[t*50 + lane]      : -1e30f;
        float z2 = (lane + 32 < K_) ? zs[t*50 + lane + 32] : -1e30f;
        float m = fmaxf(z1, z2);
        #pragma unroll
        for (int o = 16; o; o >>= 1) m = fmaxf(m, __shfl_xor_sync(0xffffffffu, m, o));
        float e1 = (lane < K_)      ? __expf(z1 - m) : 0.f;
        float e2 = (lane + 32 < K_) ? __expf(z2 - m) : 0.f;
        float s = e1 + e2;
        #pragma unroll
        for (int o = 16; o; o >>= 1) s += __shfl_xor_sync(0xffffffffu, s, o);
        float inv = 1.f / s;
        size_t bt = (size_t)b * T_ + t0 + t;
        float a1v = e1 * inv, a2v = e2 * inv;
        if (lane < K_) {
            out_alpha[bt * K_ + lane] = a1v;
            zs[t*50 + lane] = a1v;                 // overwrite z with alpha
        }
        if (lane + 32 < K_) {
            out_alpha[bt * K_ + lane + 32] = a2v;
            zs[t*50 + lane + 32] = a2v;
        }
        if (lane == 0) {
            float ze = zes[t];
            float m2 = fmaxf(m, ze);
            float ee = __expf(ze - m2);
            float denom = s * __expf(m - m2) + ee;
            out_beta[bt] = ee / denom;
        }
    }
    __syncthreads();

    // Emit interleaved (hi,lo) alpha pairs: [bt][32 kpairs], kpairs >= 25 zero.
    for (int item = tid; item < TZ * 32; item += 256) {
        int t = item >> 5, kp = item & 31;
        float x0 = (2*kp     < K_) ? zs[t*50 + 2*kp]     : 0.f;
        float x1 = (2*kp + 1 < K_) ? zs[t*50 + 2*kp + 1] : 0.f;
        uint32_t h, l;
        bf2split(x0, x1, h, l);
        g_ahl[((size_t)b * T_ + t0 + t) * 32 + kp] = ((u64)l << 32) | h;
    }
}

// ---------------------------------------------------------------------------
// chat via 2-term bf16-split m16n8k16 mma with INTERLEAVED (hi,lo) u64 smem
// tiles: every fragment pair is one LDS.64 (mainloop LDS halved: 40->20/kstep).
// Grid (4, B) = 1024 blocks. V pitch 132 u64, A pitch 36 u64 (both verified
// conflict-free per LDS.64 half-warp phase).
// ---------------------------------------------------------------------------
#define VPU2 132           // u64 pitch of V tile [32 kpairs][128 n]
#define APU2 36            // u64 pitch of A tile [64 t][32 kpairs]
#define V_U64 (32 * VPU2)  // 4224
#define A_U64 (64 * APU2)  // 2304
#define SMEM_CHAT ((V_U64 + A_U64) * 8 + 64 * 4)   // 52480 bytes

__global__ __launch_bounds__(256)
void chat_mma_kernel(const float* __restrict__ V, const float* __restrict__ s_t,
                     const float* __restrict__ beta, float* __restrict__ out)
{
    extern __shared__ __align__(16) u64 csm[];
    u64*   VHL = csm;                       // [32][VPU2]
    u64*   AHL = csm + V_U64;               // [64][APU2]
    float* bsm = (float*)(csm + V_U64 + A_U64);

    const int b  = blockIdx.y;
    const int hc = blockIdx.x * 128;
    const int tid = threadIdx.x;
    const uint32_t ahl_u = s2u(AHL);

    // Prefetch the epilogue's s_t working set into L2.
    {
        int t = tid >> 2, ln = tid & 3;
        prefetchL2(&s_t[((size_t)b * T_ + t) * H_ + hc + ln * 32]);
    }

    // Alpha (hi,lo) tile via cp.async: 64 rows x 16 16B-chunks (2 u64 each).
    #pragma unroll
    for (int i = 0; i < 4; i++) {
        int idx = tid + i * 256;
        int row = idx >> 4, c2 = (idx & 15) * 2;
        cpa16(ahl_u + (uint32_t)(row * APU2 + c2) * 8,
              &g_ahl[((size_t)b * T_ + row) * 32 + c2]);
    }
    asm volatile("cp.async.commit_group;" ::: "memory");

    // V tile: 25 kpairs x 32 float4-cols, split to interleaved (hi,lo) u64.
    for (int idx = tid; idx < 25 * 32; idx += 256) {
        int kp = idx >> 5, n4 = idx & 31;
        const float* p0 = &V[((size_t)b * K_ + 2 * kp) * H_ + hc + n4 * 4];
        float4 x0 = *(const float4*)p0;
        float4 x1 = make_float4(0.f, 0.f, 0.f, 0.f);
        if (2 * kp + 1 < K_) x1 = *(const float4*)(p0 + H_);
        uint4 h, l;
        bf2split(x0.x, x1.x, h.x, l.x);
        bf2split(x0.y, x1.y, h.y, l.y);
        bf2split(x0.z, x1.z, h.z, l.z);
        bf2split(x0.w, x1.w, h.w, l.w);
        uint4 u0 = make_uint4(h.x, l.x, h.y, l.y);
        uint4 u1 = make_uint4(h.z, l.z, h.w, l.w);
        *(uint4*)&VHL[kp * VPU2 + n4 * 4]     = u0;
        *(uint4*)&VHL[kp * VPU2 + n4 * 4 + 2] = u1;
    }
    // Zero pad kpairs 25..31 (7 rows x 128 u64 = 448 uint4).
    for (int idx = tid; idx < 448; idx += 256) {
        int kp = 25 + idx / 64, c = idx % 64;
        *(uint4*)&VHL[kp * VPU2 + c * 2] = make_uint4(0, 0, 0, 0);
    }
    if (tid < T_) bsm[tid] = beta[(size_t)b * T_ + tid];
    asm volatile("cp.async.wait_group 0;" ::: "memory");
    __syncthreads();

    const int wid  = tid >> 5;
    const int lane = tid & 31;
    const int g    = lane >> 2;
    const int tg   = lane & 3;
    const int mw   = wid & 3;
    const int nh   = wid >> 2;
    const int row  = 16 * mw + g;

    float acc[8][4];
    #pragma unroll
    for (int j = 0; j < 8; j++)
        #pragma unroll
        for (int c = 0; c < 4; c++) acc[j][c] = 0.f;

    #pragma unroll
    for (int ks = 0; ks < 4; ks++) {
        uint2 aA = *(const uint2*)&AHL[ row      * APU2 + ks*8 + tg    ];
        uint2 aB = *(const uint2*)&AHL[(row + 8) * APU2 + ks*8 + tg    ];
        uint2 aC = *(const uint2*)&AHL[ row      * APU2 + ks*8 + tg + 4];
        uint2 aD = *(const uint2*)&AHL[(row + 8) * APU2 + ks*8 + tg + 4];
        #pragma unroll
        for (int j = 0; j < 8; j++) {
            int n = nh*64 + j*8 + g;
            uint2 b0 = *(const uint2*)&VHL[(ks*8 + tg    ) * VPU2 + n];
            uint2 b1 = *(const uint2*)&VHL[(ks*8 + tg + 4) * VPU2 + n];
            mma_bf16(acc[j], aA.x, aB.x, aC.x, aD.x, b0.x, b1.x);   // hi*hi
            mma_bf16(acc[j], aA.x, aB.x, aC.x, aD.x, b0.y, b1.y);   // hi*lo
            mma_bf16(acc[j], aA.y, aB.y, aC.y, aD.y, b0.x, b1.x);   // lo*hi
        }
    }

    const float bv0 = bsm[row],     ob0 = 1.f - bv0;
    const float bv1 = bsm[row + 8], ob1 = 1.f - bv1;
    #pragma unroll
    for (int j = 0; j < 8; j++) {
        int col = hc + nh*64 + j*8 + 2*tg;
        size_t base0 = ((size_t)b * T_ + row)     * H_ + col;
        size_t base1 = ((size_t)b * T_ + row + 8) * H_ + col;
        float2 s0 = *(const float2*)&s_t[base0];
        float2 s1 = *(const float2*)&s_t[base1];
        float2 o0, o1;
        o0.x = fmaf(bv0, s0.x, ob0 * acc[j][0]);
        o0.y = fmaf(bv0, s0.y, ob0 * acc[j][1]);
        o1.x = fmaf(bv1, s1.x, ob1 * acc[j][2]);
        o1.y = fmaf(bv1, s1.y, ob1 * acc[j][3]);
        *(float2*)&out[base0] = o0;
        *(float2*)&out[base1] = o1;
    }
}

extern "C" void kernel_launch(void* const* d_in, const int* in_sizes, int n_in,
                              void* d_out, int out_size)
{
    (void)in_sizes; (void)n_in; (void)out_size;
    const float* V   = (const float*)d_in[0];   // (B,K,H)
    const float* h_t = (const float*)d_in[1];   // (B,T,H)
    const float* s_t = (const float*)d_in[2];   // (B,T,H)
    const float* Wv  = (const float*)d_in[3];   // (K,H)
    const float* Wg  = (const float*)d_in[4];   // (K,H)
    const float* Ws_ = (const float*)d_in[5];   // (K,H)
    const float* Wh  = (const float*)d_in[6];   // (1,K)

    float* out       = (float*)d_out;
    float* out_chat  = out;                 // (B,T,H)
    float* out_alpha = out + BTH;           // (B,T,K)
    float* out_beta  = out + BTH + BTK;     // (B,T,1)

    cudaFuncSetAttribute(chat_mma_kernel,
                         cudaFuncAttributeMaxDynamicSharedMemorySize, SMEM_CHAT);

    wperm_kernel<<<192, 128>>>(Wv, Wg, Ws_);
    gemm_mma_kernel<<<708, 128>>>(V, h_t, s_t);
    zsoft_kernel<<<dim3(4, B_), 256>>>(Wh, out_alpha, out_beta);
    chat_mma_kernel<<<dim3(4, B_), 256, SMEM_CHAT>>>(V, s_t, out_beta, out_chat);
}

// round 15
// speedup vs baseline: 1.1118x; 1.0329x over previous
#include <cuda_runtime.h>
#include <cstdint>

// Problem dims
#define B_  256
#define T_  64
#define K_  49
#define H_  512
#define A_  49
#define BT  (B_ * T_)            // 16384
#define BK  (B_ * K_)            // 12544
#define BTH ((size_t)BT * H_)    // 8388608
#define BTK ((size_t)BT * K_)    // 802816
#define CP  52                   // padded row pitch for scratch [*, 52]

typedef unsigned long long u64;

// Scratch (device globals; no allocations allowed)
__device__ __align__(16) float    g_cv[B_ * K_ * CP];   // content_v  [b,k,52]
__device__ __align__(16) float    g_cg[B_ * T_ * CP];   // content_g  [b,t,52]
__device__ __align__(16) float    g_cs[B_ * T_ * CP];   // s_t@Ws^T   [b,t,52]
__device__ __align__(16) float    g_Wp[3 * 32768];      // permuted W fragments
__device__ __align__(16) uint32_t g_ahi[BT * 32];       // alpha hi bf16x2 [bt][kpair]
__device__ __align__(16) uint32_t g_alo[BT * 32];       // alpha lo bf16x2 [bt][kpair]

__device__ __forceinline__ float tanh_approx(float x) {
    float y;
    asm("tanh.approx.f32 %0, %1;" : "=f"(y) : "f"(x));
    return y;
}
__device__ __forceinline__ u64 pack2(float lo, float hi) {
    u64 d;
    asm("mov.b64 %0, {%1, %2};" : "=l"(d) : "f"(lo), "f"(hi));
    return d;
}
__device__ __forceinline__ uint32_t s2u(const void* p) {
    uint32_t a;
    asm("{ .reg .u64 t; cvta.to.shared.u64 t, %1; cvt.u32.u64 %0, t; }"
        : "=r"(a) : "l"(p));
    return a;
}
__device__ __forceinline__ void cpa16(uint32_t dst, const void* src) {
    asm volatile("cp.async.cg.shared.global [%0], [%1], 16;"
                 :: "r"(dst), "l"(src) : "memory");
}
__device__ __forceinline__ void prefetchL2(const void* p) {
    asm volatile("prefetch.global.L2 [%0];" :: "l"(p));
}
__device__ __forceinline__ void gdc_wait() {
    asm volatile("griddepcontrol.wait;" ::: "memory");
}
__device__ __forceinline__ void gdc_launch_dependents() {
    asm volatile("griddepcontrol.launch_dependents;" ::: "memory");
}
__device__ __forceinline__ void mma_tf32(float* d,
                                         float a0, float a1, float a2, float a3,
                                         float b0, float b1) {
    asm volatile(
        "mma.sync.aligned.m16n8k8.row.col.f32.tf32.tf32.f32 "
        "{%0,%1,%2,%3}, {%4,%5,%6,%7}, {%8,%9}, {%0,%1,%2,%3};"
        : "+f"(d[0]), "+f"(d[1]), "+f"(d[2]), "+f"(d[3])
        : "r"(__float_as_uint(a0)), "r"(__float_as_uint(a1)),
          "r"(__float_as_uint(a2)), "r"(__float_as_uint(a3)),
          "r"(__float_as_uint(b0)), "r"(__float_as_uint(b1)));
}
__device__ __forceinline__ void mma_bf16(float* d,
                                         uint32_t a0, uint32_t a1, uint32_t a2, uint32_t a3,
                                         uint32_t b0, uint32_t b1) {
    asm volatile(
        "mma.sync.aligned.m16n8k16.row.col.f32.bf16.bf16.f32 "
        "{%0,%1,%2,%3}, {%4,%5,%6,%7}, {%8,%9}, {%0,%1,%2,%3};"
        : "+f"(d[0]), "+f"(d[1]), "+f"(d[2]), "+f"(d[3])
        : "r"(a0), "r"(a1), "r"(a2), "r"(a3), "r"(b0), "r"(b1));
}
__device__ __forceinline__ uint32_t bf2pack(float x0, float x1) {
    uint32_t h;
    asm("cvt.rn.bf16x2.f32 %0, %1, %2;" : "=r"(h) : "f"(x1), "f"(x0));
    return h;
}
__device__ __forceinline__ void bf2split(float x0, float x1,
                                         uint32_t& hi, uint32_t& lo) {
    hi = bf2pack(x0, x1);
    float r0 = __uint_as_float(hi << 16);
    float r1 = __uint_as_float(hi & 0xffff0000u);
    lo = bf2pack(x0 - r0, x1 - r1);
}

// ---------------------------------------------------------------------------
// Permute W matrices into mma.sync B-fragment order.
// ---------------------------------------------------------------------------
__global__ __launch_bounds__(128)
void wperm_kernel(const float* __restrict__ Wv, const float* __restrict__ Wg,
                  const float* __restrict__ Ws_)
{
    int tid = blockIdx.x * 128 + threadIdx.x;       // 0..24575
    int mat = tid / 8192;
    int rem = tid % 8192;
    int S   = rem / 128;
    int j   = (rem / 32) % 4;
    int l   = rem % 32;
    int g = l >> 2, tg = l & 3;
    int k = S * 8 + tg;
    int r0 = 16 * j + g, r1 = r0 + 8;
    const float* W = (mat == 0) ? Wv : (mat == 1) ? Wg : Ws_;
    float4 F;
    F.x = (r0 < A_) ? W[(size_t)r0 * H_ + k]     : 0.f;
    F.y = (r0 < A_) ? W[(size_t)r0 * H_ + k + 4] : 0.f;
    F.z = (r1 < A_) ? W[(size_t)r1 * H_ + k]     : 0.f;
    F.w = (r1 < A_) ? W[(size_t)r1 * H_ + k + 4] : 0.f;
    *(float4*)&g_Wp[(size_t)mat * 32768 + (size_t)rem * 4] = F;
    gdc_launch_dependents();
}

// ---------------------------------------------------------------------------
// tf32 mma.sync content GEMM, double-buffered K=32 chunks, 6 CTA/SM (1 wave).
// PDL: waits on wperm at start, triggers zsoft at end.
// ---------------------------------------------------------------------------
#define XPW 36     // X smem pitch (floats)

__global__ __launch_bounds__(128, 6)
void gemm_mma_kernel(const float* __restrict__ V,   const float* __restrict__ h_t,
                     const float* __restrict__ s_t)
{
    __shared__ __align__(16) float Xs[2][64][XPW];
    __shared__ __align__(16) float Bs[2][2048];

    const float* X; const float* wp; float* out; int row0;
    const int bid = blockIdx.x;
    if (bid < 196)      { X = V;   wp = g_Wp;          out = g_cv; row0 = bid * 64; }
    else if (bid < 452) { X = h_t; wp = g_Wp + 32768;  out = g_cg; row0 = (bid - 196) * 64; }
    else                { X = s_t; wp = g_Wp + 65536;  out = g_cs; row0 = (bid - 452) * 64; }

    const int tid  = threadIdx.x;
    const int wid  = tid >> 5;
    const int lane = tid & 31;
    const int g    = lane >> 2;
    const int tg   = lane & 3;
    const uint32_t xs_u[2] = { s2u(&Xs[0][0][0]), s2u(&Xs[1][0][0]) };
    const uint32_t bs_u[2] = { s2u(&Bs[0][0]),    s2u(&Bs[1][0]) };

    auto load_x = [&](int c) {
        const int p = c & 1;
        #pragma unroll
        for (int i = 0; i < 4; i++) {
            int idx = tid + i * 128;
            int r = idx >> 3, c4 = idx & 7;
            cpa16(xs_u[p] + (uint32_t)(r * XPW + c4 * 4) * 4,
                  &X[(size_t)(row0 + r) * H_ + c * 32 + c4 * 4]);
        }
    };
    auto load_b = [&](int c) {
        const int p = c & 1;
        #pragma unroll
        for (int i = 0; i < 4; i++) {
            int idx = tid + i * 128;
            cpa16(bs_u[p] + (uint32_t)idx * 16, wp + (size_t)c * 2048 + (size_t)idx * 4);
        }
    };

    float acc[8][4];
    #pragma unroll
    for (int n = 0; n < 8; n++)
        #pragma unroll
        for (int c = 0; c < 4; c++) acc[n][c] = 0.f;

    // Pre-wait: chunk-0 X loads are independent of wperm.
    load_x(0);
    gdc_wait();                 // g_Wp ready beyond this point
    load_b(0);
    asm volatile("cp.async.commit_group;" ::: "memory");

    for (int c = 0; c < 16; c++) {
        if (c + 1 < 16) {
            load_x(c + 1);
            load_b(c + 1);
            asm volatile("cp.async.commit_group;" ::: "memory");
            asm volatile("cp.async.wait_group 1;" ::: "memory");
        } else {
            asm volatile("cp.async.wait_group 0;" ::: "memory");
        }
        __syncthreads();

        const int p = c & 1;
        #pragma unroll
        for (int s = 0; s < 4; s++) {
            float a0 = Xs[p][16*wid + g    ][s*8 + tg    ];
            float a1 = Xs[p][16*wid + g + 8][s*8 + tg    ];
            float a2 = Xs[p][16*wid + g    ][s*8 + tg + 4];
            float a3 = Xs[p][16*wid + g + 8][s*8 + tg + 4];
            #pragma unroll
            for (int j = 0; j < 4; j++) {
                float4 bf = *(const float4*)&Bs[p][((s*4 + j) * 32 + lane) * 4];
                mma_tf32(acc[2*j],     a0, a1, a2, a3, bf.x, bf.y);
                mma_tf32(acc[2*j + 1], a0, a1, a2, a3, bf.z, bf.w);
            }
        }
        __syncthreads();
    }

    const int r0g = row0 + 16 * wid + g;
    #pragma unroll
    for (int n = 0; n < 8; n++) {
        int col0 = n * 8 + tg * 2;
        if (col0 < CP) {
            *(u64*)&out[(size_t)r0g * CP + col0]       = pack2(acc[n][0], acc[n][1]);
            *(u64*)&out[(size_t)(r0g + 8) * CP + col0] = pack2(acc[n][2], acc[n][3]);
        }
    }
    gdc_launch_dependents();
}

// ---------------------------------------------------------------------------
// zsoft: z_t + z_ext + softmax(alpha) + extended softmax(beta).
// Emits pre-split bf16 hi/lo alpha tiles (g_ahi/g_alo) for chat.
// PDL: waits on gemm, triggers chat.
// ---------------------------------------------------------------------------
#define TZ 16
#define ZP 52

__global__ __launch_bounds__(256)
void zsoft_kernel(const float* __restrict__ Wh,
                  float* __restrict__ out_alpha, float* __restrict__ out_beta)
{
    const int b  = blockIdx.y;
    const int t0 = blockIdx.x * TZ;
    __shared__ __align__(16) float cvs[K_ * ZP];
    __shared__ __align__(16) float cgs[TZ * ZP];
    __shared__ __align__(16) float css[TZ * ZP];
    __shared__ __align__(16) float whs[52];
    __shared__ float zes[TZ];
    __shared__ float zs[TZ * 50];
    const int tid = threadIdx.x;

    if (tid < 52) whs[tid] = (tid < A_) ? Wh[tid] : 0.f;   // pre-wait (input)
    gdc_wait();                 // g_cv/g_cg/g_cs ready beyond this point

    for (int i = tid; i < K_ * 13; i += 256) {
        int k = i / 13, c4 = i % 13;
        *(float4*)&cvs[k * ZP + c4*4] =
            *(const float4*)&g_cv[((size_t)b * K_ + k) * CP + c4*4];
    }
    for (int i = tid; i < TZ * 13; i += 256) {
        int t = i / 13, c4 = i % 13;
        size_t src = ((size_t)b * T_ + t0 + t) * CP + c4*4;
        *(float4*)&cgs[t * ZP + c4*4] = *(const float4*)&g_cg[src];
        *(float4*)&css[t * ZP + c4*4] = *(const float4*)&g_cs[src];
    }
    __syncthreads();

    for (int item = tid; item < TZ * K_ + TZ; item += 256) {
        const float* rowA;
        const float* rowB;
        if (item < TZ * K_) {
            int t = item / K_, k = item % K_;
            rowA = &cgs[t * ZP];
            rowB = &cvs[k * ZP];
        } else {
            int t = item - TZ * K_;
            rowA = &cgs[t * ZP];
            rowB = &css[t * ZP];
        }
        float s0 = 0.f, s1 = 0.f, s2 = 0.f, s3 = 0.f;
        #pragma unroll
        for (int a = 0; a < 48; a += 4) {
            float4 A = *(const float4*)&rowA[a];
            float4 Bv = *(const float4*)&rowB[a];
            float4 W = *(const float4*)&whs[a];
            s0 = fmaf(tanh_approx(A.x + Bv.x), W.x, s0);
            s1 = fmaf(tanh_approx(A.y + Bv.y), W.y, s1);
            s2 = fmaf(tanh_approx(A.z + Bv.z), W.z, s2);
            s3 = fmaf(tanh_approx(A.w + Bv.w), W.w, s3);
        }
        s0 = fmaf(tanh_approx(rowA[48] + rowB[48]), whs[48], s0);
        float z = (s0 + s1) + (s2 + s3);
        if (item < TZ * K_) {
            int t = item / K_, k = item % K_;
            zs[t * 50 + k] = z;
        } else {
            zes[item - TZ * K_] = z;
        }
    }
    __syncthreads();

    const int warp = tid >> 5, lane = tid & 31;
    for (int t = warp; t < TZ; t += 8) {
        float z1 = (lane < K_)      ? zs[t*50 + lane]      : -1e30f;
        float z2 = (lane + 32 < K_) ? zs[t*50 + lane + 32] : -1e30f;
        float m = fmaxf(z1, z2);
        #pragma unroll
        for (int o = 16; o; o >>= 1) m = fmaxf(m, __shfl_xor_sync(0xffffffffu, m, o));
        float e1 = (lane < K_)      ? __expf(z1 - m) : 0.f;
        float e2 = (lane + 32 < K_) ? __expf(z2 - m) : 0.f;
        float s = e1 + e2;
        #pragma unroll
        for (int o = 16; o; o >>= 1) s += __shfl_xor_sync(0xffffffffu, s, o);
        float inv = 1.f / s;
        size_t bt = (size_t)b * T_ + t0 + t;
        float a1v = e1 * inv, a2v = e2 * inv;
        if (lane < K_) {
            out_alpha[bt * K_ + lane] = a1v;
            zs[t*50 + lane] = a1v;                 // overwrite z with alpha
        }
        if (lane + 32 < K_) {
            out_alpha[bt * K_ + lane + 32] = a2v;
            zs[t*50 + lane + 32] = a2v;
        }
        if (lane == 0) {
            float ze = zes[t];
            float m2 = fmaxf(m, ze);
            float ee = __expf(ze - m2);
            float denom = s * __expf(m - m2) + ee;
            out_beta[bt] = ee / denom;
        }
    }
    __syncthreads();

    // Emit pre-split bf16 alpha tiles: [bt][32 kpairs], kpairs >= 25 zero.
    for (int item = tid; item < TZ * 32; item += 256) {
        int t = item >> 5, kp = item & 31;
        float x0 = (2*kp     < K_) ? zs[t*50 + 2*kp]     : 0.f;
        float x1 = (2*kp + 1 < K_) ? zs[t*50 + 2*kp + 1] : 0.f;
        uint32_t h, l;
        bf2split(x0, x1, h, l);
        size_t dst = ((size_t)b * T_ + t0 + t) * 32 + kp;
        g_ahi[dst] = h;
        g_alo[dst] = l;
    }
    gdc_launch_dependents();
}

// ---------------------------------------------------------------------------
// chat via 2-term bf16-split m16n8k16 mma (round-12 structure). PDL: the V
// load + bf16 split (independent of zsoft) runs PRE-wait, overlapping the
// zsoft tail; alpha/beta loads happen post-wait.
// ---------------------------------------------------------------------------
#define VPU 136            // u32 pitch of V hi/lo tiles [32 kpairs][128 n]
#define APU 36             // u32 pitch of A hi/lo tiles [64 t][32 kpairs]
#define V_U32 (32 * VPU)   // 4352
#define A_U32 (64 * APU)   // 2304
#define SMEM_CHAT ((2 * V_U32 + 2 * A_U32 + 64) * 4)   // 53504 bytes

__global__ __launch_bounds__(256)
void chat_mma_kernel(const float* __restrict__ V, const float* __restrict__ s_t,
                     const float* __restrict__ beta, float* __restrict__ out)
{
    extern __shared__ __align__(16) uint32_t csm[];
    uint32_t* Vhi = csm;
    uint32_t* Vlo = csm + V_U32;
    uint32_t* Ahi = csm + 2 * V_U32;
    uint32_t* Alo = csm + 2 * V_U32 + A_U32;
    float*    bsm = (float*)(csm + 2 * V_U32 + 2 * A_U32);

    const int b  = blockIdx.y;
    const int hc = blockIdx.x * 128;
    const int tid = threadIdx.x;
    const uint32_t ahi_u = s2u(Ahi);
    const uint32_t alo_u = s2u(Alo);

    // ---- PRE-WAIT section: V, s_t only (independent of zsoft) ----
    {
        int t = tid >> 2, ln = tid & 3;
        prefetchL2(&s_t[((size_t)b * T_ + t) * H_ + hc + ln * 32]);
    }
    // V tile: 25 kpairs x 32 float4-cols (k >= 49 zero), split to hi/lo.
    for (int idx = tid; idx < 25 * 32; idx += 256) {
        int kp = idx >> 5, n4 = idx & 31;
        const float* p0 = &V[((size_t)b * K_ + 2 * kp) * H_ + hc + n4 * 4];
        float4 x0 = *(const float4*)p0;
        float4 x1 = make_float4(0.f, 0.f, 0.f, 0.f);
        if (2 * kp + 1 < K_) x1 = *(const float4*)(p0 + H_);
        uint4 h, l;
        bf2split(x0.x, x1.x, h.x, l.x);
        bf2split(x0.y, x1.y, h.y, l.y);
        bf2split(x0.z, x1.z, h.z, l.z);
        bf2split(x0.w, x1.w, h.w, l.w);
        *(uint4*)&Vhi[kp * VPU + n4 * 4] = h;
        *(uint4*)&Vlo[kp * VPU + n4 * 4] = l;
    }
    for (int idx = tid; idx < 2 * 7 * 32; idx += 256) {
        int p = idx / 224, r = idx % 224;
        int kp = 25 + r / 32, n4 = r % 32;
        uint32_t* dst = p ? Vlo : Vhi;
        *(uint4*)&dst[kp * VPU + n4 * 4] = make_uint4(0, 0, 0, 0);
    }

    // ---- WAIT for zsoft (alpha/beta producers) ----
    gdc_wait();

    // Alpha hi/lo tiles via cp.async: 64 rows x 8 16B-chunks each.
    #pragma unroll
    for (int i = 0; i < 2; i++) {
        int idx = tid + i * 256;
        int row = idx >> 3, c4 = idx & 7;
        cpa16(ahi_u + (uint32_t)(row * APU + c4 * 4) * 4,
              &g_ahi[((size_t)b * T_ + row) * 32 + c4 * 4]);
        cpa16(alo_u + (uint32_t)(row * APU + c4 * 4) * 4,
              &g_alo[((size_t)b * T_ + row) * 32 + c4 * 4]);
    }
    asm volatile("cp.async.commit_group;" ::: "memory");
    if (tid < T_) bsm[tid] = beta[(size_t)b * T_ + tid];
    asm volatile("cp.async.wait_group 0;" ::: "memory");
    __syncthreads();

    const int wid  = tid >> 5;
    const int lane = tid & 31;
    const int g    = lane >> 2;
    const int tg   = lane & 3;
    const int mw   = wid & 3;
    const int nh   = wid >> 2;
    const int row  = 16 * mw + g;

    float acc[8][4];
    #pragma unroll
    for (int j = 0; j < 8; j++)
        #pragma unroll
        for (int c = 0; c < 4; c++) acc[j][c] = 0.f;

    #pragma unroll
    for (int ks = 0; ks < 4; ks++) {
        uint32_t ah0 = Ahi[ row      * APU + ks*8 + tg    ];
        uint32_t ah1 = Ahi[(row + 8) * APU + ks*8 + tg    ];
        uint32_t ah2 = Ahi[ row      * APU + ks*8 + tg + 4];
        uint32_t ah3 = Ahi[(row + 8) * APU + ks*8 + tg + 4];
        uint32_t al0 = Alo[ row      * APU + ks*8 + tg    ];
        uint32_t al1 = Alo[(row + 8) * APU + ks*8 + tg    ];
        uint32_t al2 = Alo[ row      * APU + ks*8 + tg + 4];
        uint32_t al3 = Alo[(row + 8) * APU + ks*8 + tg + 4];
        #pragma unroll
        for (int j = 0; j < 8; j++) {
            int n = nh*64 + j*8 + g;
            uint32_t bh0 = Vhi[(ks*8 + tg    ) * VPU + n];
            uint32_t bh1 = Vhi[(ks*8 + tg + 4) * VPU + n];
            uint32_t bl0 = Vlo[(ks*8 + tg    ) * VPU + n];
            uint32_t bl1 = Vlo[(ks*8 + tg + 4) * VPU + n];
            mma_bf16(acc[j], ah0, ah1, ah2, ah3, bh0, bh1);   // hi*hi
            mma_bf16(acc[j], ah0, ah1, ah2, ah3, bl0, bl1);   // hi*lo
            mma_bf16(acc[j], al0, al1, al2, al3, bh0, bh1);   // lo*hi
        }
    }

    const float bv0 = bsm[row],     ob0 = 1.f - bv0;
    const float bv1 = bsm[row + 8], ob1 = 1.f - bv1;
    #pragma unroll
    for (int j = 0; j < 8; j++) {
        int col = hc + nh*64 + j*8 + 2*tg;
        size_t base0 = ((size_t)b * T_ + row)     * H_ + col;
        size_t base1 = ((size_t)b * T_ + row + 8) * H_ + col;
        float2 s0 = *(const float2*)&s_t[base0];
        float2 s1 = *(const float2*)&s_t[base1];
        float2 o0, o1;
        o0.x = fmaf(bv0, s0.x, ob0 * acc[j][0]);
        o0.y = fmaf(bv0, s0.y, ob0 * acc[j][1]);
        o1.x = fmaf(bv1, s1.x, ob1 * acc[j][2]);
        o1.y = fmaf(bv1, s1.y, ob1 * acc[j][3]);
        *(float2*)&out[base0] = o0;
        *(float2*)&out[base1] = o1;
    }
}

// ---------------------------------------------------------------------------
// Host launch with PDL (programmatic stream serialization) on consumers.
// ---------------------------------------------------------------------------
static void launch_pdl(const void* func, dim3 grid, dim3 block, size_t smem,
                       void** args)
{
    cudaLaunchConfig_t cfg = {};
    cfg.gridDim = grid;
    cfg.blockDim = block;
    cfg.dynamicSmemBytes = smem;
    cudaLaunchAttribute attr[1];
    attr[0].id = cudaLaunchAttributeProgrammaticStreamSerialization;
    attr[0].val.programmaticStreamSerializationAllowed = 1;
    cfg.attrs = attr;
    cfg.numAttrs = 1;
    cudaLaunchKernelExC(&cfg, func, args);
}

extern "C" void kernel_launch(void* const* d_in, const int* in_sizes, int n_in,
                              void* d_out, int out_size)
{
    (void)in_sizes; (void)n_in; (void)out_size;
    const float* V   = (const float*)d_in[0];   // (B,K,H)
    const float* h_t = (const float*)d_in[1];   // (B,T,H)
    const float* s_t = (const float*)d_in[2];   // (B,T,H)
    const float* Wv  = (const float*)d_in[3];   // (K,H)
    const float* Wg  = (const float*)d_in[4];   // (K,H)
    const float* Ws_ = (const float*)d_in[5];   // (K,H)
    const float* Wh  = (const float*)d_in[6];   // (1,K)

    float* out       = (float*)d_out;
    float* out_chat  = out;                 // (B,T,H)
    float* out_alpha = out + BTH;           // (B,T,K)
    float* out_beta  = out + BTH + BTK;     // (B,T,1)

    cudaFuncSetAttribute(chat_mma_kernel,
                         cudaFuncAttributeMaxDynamicSharedMemorySize, SMEM_CHAT);

    wperm_kernel<<<192, 128>>>(Wv, Wg, Ws_);

    {
        void* args[] = { (void*)&V, (void*)&h_t, (void*)&s_t };
        launch_pdl((const void*)gemm_mma_kernel, dim3(708), dim3(128), 0, args);
    }
    {
        void* args[] = { (void*)&Wh, (void*)&out_alpha, (void*)&out_beta };
        launch_pdl((const void*)zsoft_kernel, dim3(4, B_), dim3(256), 0, args);
    }
    {
        void* args[] = { (void*)&V, (void*)&s_t, (void*)&out_beta, (void*)&out_chat };
        launch_pdl((const void*)chat_mma_kernel, dim3(4, B_), dim3(256), SMEM_CHAT, args);
    }
}

// round 16
// speedup vs baseline: 1.1365x; 1.0222x over previous
#include <cuda_runtime.h>
#include <cstdint>

// Problem dims
#define B_  256
#define T_  64
#define K_  49
#define H_  512
#define A_  49
#define BT  (B_ * T_)            // 16384
#define BK  (B_ * K_)            // 12544
#define BTH ((size_t)BT * H_)    // 8388608
#define BTK ((size_t)BT * K_)    // 802816
#define CP  52                   // padded row pitch for scratch [*, 52]

typedef unsigned long long u64;

// Scratch (device globals; no allocations allowed)
__device__ __align__(16) float    g_cv[B_ * K_ * CP];   // content_v  [b,k,52]
__device__ __align__(16) float    g_cg[B_ * T_ * CP];   // content_g  [b,t,52]
__device__ __align__(16) float    g_cs[B_ * T_ * CP];   // s_t@Ws^T   [b,t,52]
__device__ __align__(16) float    g_Wp[3 * 32768];      // permuted W fragments
__device__ __align__(16) uint32_t g_ahi[BT * 32];       // alpha hi bf16x2 [bt][kpair]
__device__ __align__(16) uint32_t g_alo[BT * 32];       // alpha lo bf16x2 [bt][kpair]

__device__ __forceinline__ float tanh_approx(float x) {
    float y;
    asm("tanh.approx.f32 %0, %1;" : "=f"(y) : "f"(x));
    return y;
}
__device__ __forceinline__ u64 pack2(float lo, float hi) {
    u64 d;
    asm("mov.b64 %0, {%1, %2};" : "=l"(d) : "f"(lo), "f"(hi));
    return d;
}
__device__ __forceinline__ uint32_t s2u(const void* p) {
    uint32_t a;
    asm("{ .reg .u64 t; cvta.to.shared.u64 t, %1; cvt.u32.u64 %0, t; }"
        : "=r"(a) : "l"(p));
    return a;
}
__device__ __forceinline__ void cpa16(uint32_t dst, const void* src) {
    asm volatile("cp.async.cg.shared.global [%0], [%1], 16;"
                 :: "r"(dst), "l"(src) : "memory");
}
__device__ __forceinline__ void prefetchL2(const void* p) {
    asm volatile("prefetch.global.L2 [%0];" :: "l"(p));
}
__device__ __forceinline__ void gdc_wait() {
    asm volatile("griddepcontrol.wait;" ::: "memory");
}
__device__ __forceinline__ void gdc_launch_dependents() {
    asm volatile("griddepcontrol.launch_dependents;" ::: "memory");
}
__device__ __forceinline__ void mma_tf32(float* d,
                                         float a0, float a1, float a2, float a3,
                                         float b0, float b1) {
    asm volatile(
        "mma.sync.aligned.m16n8k8.row.col.f32.tf32.tf32.f32 "
        "{%0,%1,%2,%3}, {%4,%5,%6,%7}, {%8,%9}, {%0,%1,%2,%3};"
        : "+f"(d[0]), "+f"(d[1]), "+f"(d[2]), "+f"(d[3])
        : "r"(__float_as_uint(a0)), "r"(__float_as_uint(a1)),
          "r"(__float_as_uint(a2)), "r"(__float_as_uint(a3)),
          "r"(__float_as_uint(b0)), "r"(__float_as_uint(b1)));
}
__device__ __forceinline__ void mma_bf16(float* d,
                                         uint32_t a0, uint32_t a1, uint32_t a2, uint32_t a3,
                                         uint32_t b0, uint32_t b1) {
    asm volatile(
        "mma.sync.aligned.m16n8k16.row.col.f32.bf16.bf16.f32 "
        "{%0,%1,%2,%3}, {%4,%5,%6,%7}, {%8,%9}, {%0,%1,%2,%3};"
        : "+f"(d[0]), "+f"(d[1]), "+f"(d[2]), "+f"(d[3])
        : "r"(a0), "r"(a1), "r"(a2), "r"(a3), "r"(b0), "r"(b1));
}
__device__ __forceinline__ uint32_t bf2pack(float x0, float x1) {
    uint32_t h;
    asm("cvt.rn.bf16x2.f32 %0, %1, %2;" : "=r"(h) : "f"(x1), "f"(x0));
    return h;
}
__device__ __forceinline__ void bf2split(float x0, float x1,
                                         uint32_t& hi, uint32_t& lo) {
    hi = bf2pack(x0, x1);
    float r0 = __uint_as_float(hi << 16);
    float r1 = __uint_as_float(hi & 0xffff0000u);
    lo = bf2pack(x0 - r0, x1 - r1);
}

// ---------------------------------------------------------------------------
// Permute W matrices into mma.sync B-fragment order.
// ---------------------------------------------------------------------------
__global__ __launch_bounds__(128)
void wperm_kernel(const float* __restrict__ Wv, const float* __restrict__ Wg,
                  const float* __restrict__ Ws_)
{
    int tid = blockIdx.x * 128 + threadIdx.x;       // 0..24575
    int mat = tid / 8192;
    int rem = tid % 8192;
    int S   = rem / 128;
    int j   = (rem / 32) % 4;
    int l   = rem % 32;
    int g = l >> 2, tg = l & 3;
    int k = S * 8 + tg;
    int r0 = 16 * j + g, r1 = r0 + 8;
    const float* W = (mat == 0) ? Wv : (mat == 1) ? Wg : Ws_;
    float4 F;
    F.x = (r0 < A_) ? W[(size_t)r0 * H_ + k]     : 0.f;
    F.y = (r0 < A_) ? W[(size_t)r0 * H_ + k + 4] : 0.f;
    F.z = (r1 < A_) ? W[(size_t)r1 * H_ + k]     : 0.f;
    F.w = (r1 < A_) ? W[(size_t)r1 * H_ + k + 4] : 0.f;
    *(float4*)&g_Wp[(size_t)mat * 32768 + (size_t)rem * 4] = F;
    gdc_launch_dependents();
}

// ---------------------------------------------------------------------------
// tf32 mma.sync content GEMM, double-buffered K=32 chunks, 6 CTA/SM (1 wave).
// PDL: waits on wperm at start, triggers zsoft at end.
// ---------------------------------------------------------------------------
#define XPW 36     // X smem pitch (floats)

__global__ __launch_bounds__(128, 6)
void gemm_mma_kernel(const float* __restrict__ V,   const float* __restrict__ h_t,
                     const float* __restrict__ s_t)
{
    __shared__ __align__(16) float Xs[2][64][XPW];
    __shared__ __align__(16) float Bs[2][2048];

    const float* X; const float* wp; float* out; int row0;
    const int bid = blockIdx.x;
    if (bid < 196)      { X = V;   wp = g_Wp;          out = g_cv; row0 = bid * 64; }
    else if (bid < 452) { X = h_t; wp = g_Wp + 32768;  out = g_cg; row0 = (bid - 196) * 64; }
    else                { X = s_t; wp = g_Wp + 65536;  out = g_cs; row0 = (bid - 452) * 64; }

    const int tid  = threadIdx.x;
    const int wid  = tid >> 5;
    const int lane = tid & 31;
    const int g    = lane >> 2;
    const int tg   = lane & 3;
    const uint32_t xs_u[2] = { s2u(&Xs[0][0][0]), s2u(&Xs[1][0][0]) };
    const uint32_t bs_u[2] = { s2u(&Bs[0][0]),    s2u(&Bs[1][0]) };

    auto load_x = [&](int c) {
        const int p = c & 1;
        #pragma unroll
        for (int i = 0; i < 4; i++) {
            int idx = tid + i * 128;
            int r = idx >> 3, c4 = idx & 7;
            cpa16(xs_u[p] + (uint32_t)(r * XPW + c4 * 4) * 4,
                  &X[(size_t)(row0 + r) * H_ + c * 32 + c4 * 4]);
        }
    };
    auto load_b = [&](int c) {
        const int p = c & 1;
        #pragma unroll
        for (int i = 0; i < 4; i++) {
            int idx = tid + i * 128;
            cpa16(bs_u[p] + (uint32_t)idx * 16, wp + (size_t)c * 2048 + (size_t)idx * 4);
        }
    };

    float acc[8][4];
    #pragma unroll
    for (int n = 0; n < 8; n++)
        #pragma unroll
        for (int c = 0; c < 4; c++) acc[n][c] = 0.f;

    // Pre-wait: chunk-0 X loads are independent of wperm.
    load_x(0);
    gdc_wait();                 // g_Wp ready beyond this point
    load_b(0);
    asm volatile("cp.async.commit_group;" ::: "memory");

    for (int c = 0; c < 16; c++) {
        if (c + 1 < 16) {
            load_x(c + 1);
            load_b(c + 1);
            asm volatile("cp.async.commit_group;" ::: "memory");
            asm volatile("cp.async.wait_group 1;" ::: "memory");
        } else {
            asm volatile("cp.async.wait_group 0;" ::: "memory");
        }
        __syncthreads();

        const int p = c & 1;
        #pragma unroll
        for (int s = 0; s < 4; s++) {
            float a0 = Xs[p][16*wid + g    ][s*8 + tg    ];
            float a1 = Xs[p][16*wid + g + 8][s*8 + tg    ];
            float a2 = Xs[p][16*wid + g    ][s*8 + tg + 4];
            float a3 = Xs[p][16*wid + g + 8][s*8 + tg + 4];
            #pragma unroll
            for (int j = 0; j < 4; j++) {
                float4 bf = *(const float4*)&Bs[p][((s*4 + j) * 32 + lane) * 4];
                mma_tf32(acc[2*j],     a0, a1, a2, a3, bf.x, bf.y);
                mma_tf32(acc[2*j + 1], a0, a1, a2, a3, bf.z, bf.w);
            }
        }
        __syncthreads();
    }

    const int r0g = row0 + 16 * wid + g;
    #pragma unroll
    for (int n = 0; n < 8; n++) {
        int col0 = n * 8 + tg * 2;
        if (col0 < CP) {
            *(u64*)&out[(size_t)r0g * CP + col0]       = pack2(acc[n][0], acc[n][1]);
            *(u64*)&out[(size_t)(r0g + 8) * CP + col0] = pack2(acc[n][2], acc[n][3]);
        }
    }
    gdc_launch_dependents();
}

// ---------------------------------------------------------------------------
// zsoft: z_t + z_ext + softmax(alpha) + extended softmax(beta).
// Emits pre-split bf16 hi/lo alpha tiles (g_ahi/g_alo) for chat.
// PDL: waits on gemm, triggers chat.
// ---------------------------------------------------------------------------
#define TZ 16
#define ZP 52

__global__ __launch_bounds__(256)
void zsoft_kernel(const float* __restrict__ Wh,
                  float* __restrict__ out_alpha, float* __restrict__ out_beta)
{
    const int b  = blockIdx.y;
    const int t0 = blockIdx.x * TZ;
    __shared__ __align__(16) float cvs[K_ * ZP];
    __shared__ __align__(16) float cgs[TZ * ZP];
    __shared__ __align__(16) float css[TZ * ZP];
    __shared__ __align__(16) float whs[52];
    __shared__ float zes[TZ];
    __shared__ float zs[TZ * 50];
    const int tid = threadIdx.x;

    if (tid < 52) whs[tid] = (tid < A_) ? Wh[tid] : 0.f;   // pre-wait (input)
    gdc_wait();                 // g_cv/g_cg/g_cs ready beyond this point

    for (int i = tid; i < K_ * 13; i += 256) {
        int k = i / 13, c4 = i % 13;
        *(float4*)&cvs[k * ZP + c4*4] =
            *(const float4*)&g_cv[((size_t)b * K_ + k) * CP + c4*4];
    }
    for (int i = tid; i < TZ * 13; i += 256) {
        int t = i / 13, c4 = i % 13;
        size_t src = ((size_t)b * T_ + t0 + t) * CP + c4*4;
        *(float4*)&cgs[t * ZP + c4*4] = *(const float4*)&g_cg[src];
        *(float4*)&css[t * ZP + c4*4] = *(const float4*)&g_cs[src];
    }
    __syncthreads();

    for (int item = tid; item < TZ * K_ + TZ; item += 256) {
        const float* rowA;
        const float* rowB;
        if (item < TZ * K_) {
            int t = item / K_, k = item % K_;
            rowA = &cgs[t * ZP];
            rowB = &cvs[k * ZP];
        } else {
            int t = item - TZ * K_;
            rowA = &cgs[t * ZP];
            rowB = &css[t * ZP];
        }
        float s0 = 0.f, s1 = 0.f, s2 = 0.f, s3 = 0.f;
        #pragma unroll
        for (int a = 0; a < 48; a += 4) {
            float4 A = *(const float4*)&rowA[a];
            float4 Bv = *(const float4*)&rowB[a];
            float4 W = *(const float4*)&whs[a];
            s0 = fmaf(tanh_approx(A.x + Bv.x), W.x, s0);
            s1 = fmaf(tanh_approx(A.y + Bv.y), W.y, s1);
            s2 = fmaf(tanh_approx(A.z + Bv.z), W.z, s2);
            s3 = fmaf(tanh_approx(A.w + Bv.w), W.w, s3);
        }
        s0 = fmaf(tanh_approx(rowA[48] + rowB[48]), whs[48], s0);
        float z = (s0 + s1) + (s2 + s3);
        if (item < TZ * K_) {
            int t = item / K_, k = item % K_;
            zs[t * 50 + k] = z;
        } else {
            zes[item - TZ * K_] = z;
        }
    }
    __syncthreads();

    const int warp = tid >> 5, lane = tid & 31;
    for (int t = warp; t < TZ; t += 8) {
        float z1 = (lane < K_)      ? zs[t*50 + lane]      : -1e30f;
        float z2 = (lane + 32 < K_) ? zs[t*50 + lane + 32] : -1e30f;
        float m = fmaxf(z1, z2);
        #pragma unroll
        for (int o = 16; o; o >>= 1) m = fmaxf(m, __shfl_xor_sync(0xffffffffu, m, o));
        float e1 = (lane < K_)      ? __expf(z1 - m) : 0.f;
        float e2 = (lane + 32 < K_) ? __expf(z2 - m) : 0.f;
        float s = e1 + e2;
        #pragma unroll
        for (int o = 16; o; o >>= 1) s += __shfl_xor_sync(0xffffffffu, s, o);
        float inv = 1.f / s;
        size_t bt = (size_t)b * T_ + t0 + t;
        float a1v = e1 * inv, a2v = e2 * inv;
        if (lane < K_) {
            out_alpha[bt * K_ + lane] = a1v;
            zs[t*50 + lane] = a1v;                 // overwrite z with alpha
        }
        if (lane + 32 < K_) {
            out_alpha[bt * K_ + lane + 32] = a2v;
            zs[t*50 + lane + 32] = a2v;
        }
        if (lane == 0) {
            float ze = zes[t];
            float m2 = fmaxf(m, ze);
            float ee = __expf(ze - m2);
            float denom = s * __expf(m - m2) + ee;
            out_beta[bt] = ee / denom;
        }
    }
    __syncthreads();

    // Emit pre-split bf16 alpha tiles: [bt][32 kpairs], kpairs >= 25 zero.
    for (int item = tid; item < TZ * 32; item += 256) {
        int t = item >> 5, kp = item & 31;
        float x0 = (2*kp     < K_) ? zs[t*50 + 2*kp]     : 0.f;
        float x1 = (2*kp + 1 < K_) ? zs[t*50 + 2*kp + 1] : 0.f;
        uint32_t h, l;
        bf2split(x0, x1, h, l);
        size_t dst = ((size_t)b * T_ + t0 + t) * 32 + kp;
        g_ahi[dst] = h;
        g_alo[dst] = l;
    }
    gdc_launch_dependents();
}

// ---------------------------------------------------------------------------
// chat via 2-term bf16-split m16n8k16 mma. V tiles hold only 25 kpairs
// (k=0..49); ks=0..2 is the normal 72-MMA loop, ks=3 is a predicated special
// step touching only kpair 24 (k=48; k=49 zero). Smem 45.9KB -> 5 CTA/SM.
// PDL: V load/split pre-wait (overlaps zsoft tail); alpha/beta post-wait.
// ---------------------------------------------------------------------------
#define VPU 136            // u32 pitch of V hi/lo tiles [25 kpairs][128 n]
#define APU 36             // u32 pitch of A hi/lo tiles [64 t][32 kpairs]
#define V_U32 (25 * VPU)   // 3400
#define A_U32 (64 * APU)   // 2304
#define SMEM_CHAT ((2 * V_U32 + 2 * A_U32 + 64) * 4)   // 45888 bytes

__global__ __launch_bounds__(256, 5)
void chat_mma_kernel(const float* __restrict__ V, const float* __restrict__ s_t,
                     const float* __restrict__ beta, float* __restrict__ out)
{
    extern __shared__ __align__(16) uint32_t csm[];
    uint32_t* Vhi = csm;
    uint32_t* Vlo = csm + V_U32;
    uint32_t* Ahi = csm + 2 * V_U32;
    uint32_t* Alo = csm + 2 * V_U32 + A_U32;
    float*    bsm = (float*)(csm + 2 * V_U32 + 2 * A_U32);

    const int b  = blockIdx.y;
    const int hc = blockIdx.x * 128;
    const int tid = threadIdx.x;
    const uint32_t ahi_u = s2u(Ahi);
    const uint32_t alo_u = s2u(Alo);

    // ---- PRE-WAIT section: V, s_t only (independent of zsoft) ----
    {
        int t = tid >> 2, ln = tid & 3;
        prefetchL2(&s_t[((size_t)b * T_ + t) * H_ + hc + ln * 32]);
    }
    // V tile: 25 kpairs x 32 float4-cols (k=49 zero), split to hi/lo.
    for (int idx = tid; idx < 25 * 32; idx += 256) {
        int kp = idx >> 5, n4 = idx & 31;
        const float* p0 = &V[((size_t)b * K_ + 2 * kp) * H_ + hc + n4 * 4];
        float4 x0 = *(const float4*)p0;
        float4 x1 = make_float4(0.f, 0.f, 0.f, 0.f);
        if (2 * kp + 1 < K_) x1 = *(const float4*)(p0 + H_);
        uint4 h, l;
        bf2split(x0.x, x1.x, h.x, l.x);
        bf2split(x0.y, x1.y, h.y, l.y);
        bf2split(x0.z, x1.z, h.z, l.z);
        bf2split(x0.w, x1.w, h.w, l.w);
        *(uint4*)&Vhi[kp * VPU + n4 * 4] = h;
        *(uint4*)&Vlo[kp * VPU + n4 * 4] = l;
    }

    // ---- WAIT for zsoft (alpha/beta producers) ----
    gdc_wait();

    // Alpha hi/lo tiles via cp.async: 64 rows x 8 16B-chunks each.
    #pragma unroll
    for (int i = 0; i < 2; i++) {
        int idx = tid + i * 256;
        int row = idx >> 3, c4 = idx & 7;
        cpa16(ahi_u + (uint32_t)(row * APU + c4 * 4) * 4,
              &g_ahi[((size_t)b * T_ + row) * 32 + c4 * 4]);
        cpa16(alo_u + (uint32_t)(row * APU + c4 * 4) * 4,
              &g_alo[((size_t)b * T_ + row) * 32 + c4 * 4]);
    }
    asm volatile("cp.async.commit_group;" ::: "memory");
    if (tid < T_) bsm[tid] = beta[(size_t)b * T_ + tid];
    asm volatile("cp.async.wait_group 0;" ::: "memory");
    __syncthreads();

    const int wid  = tid >> 5;
    const int lane = tid & 31;
    const int g    = lane >> 2;
    const int tg   = lane & 3;
    const int mw   = wid & 3;
    const int nh   = wid >> 2;
    const int row  = 16 * mw + g;

    float acc[8][4];
    #pragma unroll
    for (int j = 0; j < 8; j++)
        #pragma unroll
        for (int c = 0; c < 4; c++) acc[j][c] = 0.f;

    // ks = 0..2: full tiles, kpairs 0..23.
    #pragma unroll
    for (int ks = 0; ks < 3; ks++) {
        uint32_t ah0 = Ahi[ row      * APU + ks*8 + tg    ];
        uint32_t ah1 = Ahi[(row + 8) * APU + ks*8 + tg    ];
        uint32_t ah2 = Ahi[ row      * APU + ks*8 + tg + 4];
        uint32_t ah3 = Ahi[(row + 8) * APU + ks*8 + tg + 4];
        uint32_t al0 = Alo[ row      * APU + ks*8 + tg    ];
        uint32_t al1 = Alo[(row + 8) * APU + ks*8 + tg    ];
        uint32_t al2 = Alo[ row      * APU + ks*8 + tg + 4];
        uint32_t al3 = Alo[(row + 8) * APU + ks*8 + tg + 4];
        #pragma unroll
        for (int j = 0; j < 8; j++) {
            int n = nh*64 + j*8 + g;
            uint32_t bh0 = Vhi[(ks*8 + tg    ) * VPU + n];
            uint32_t bh1 = Vhi[(ks*8 + tg + 4) * VPU + n];
            uint32_t bl0 = Vlo[(ks*8 + tg    ) * VPU + n];
            uint32_t bl1 = Vlo[(ks*8 + tg + 4) * VPU + n];
            mma_bf16(acc[j], ah0, ah1, ah2, ah3, bh0, bh1);   // hi*hi
            mma_bf16(acc[j], ah0, ah1, ah2, ah3, bl0, bl1);   // hi*lo
            mma_bf16(acc[j], al0, al1, al2, al3, bh0, bh1);   // lo*hi
        }
    }

    // ks = 3: only kpair 24 is real (k=48; 49 zero). Lanes tg==0 carry it.
    {
        uint32_t ah0 = 0, ah1 = 0, al0 = 0, al1 = 0;
        if (tg == 0) {
            ah0 = Ahi[ row      * APU + 24];
            ah1 = Ahi[(row + 8) * APU + 24];
            al0 = Alo[ row      * APU + 24];
            al1 = Alo[(row + 8) * APU + 24];
        }
        #pragma unroll
        for (int j = 0; j < 8; j++) {
            int n = nh*64 + j*8 + g;
            uint32_t bh0 = 0, bl0 = 0;
            if (tg == 0) {
                bh0 = Vhi[24 * VPU + n];
                bl0 = Vlo[24 * VPU + n];
            }
            mma_bf16(acc[j], ah0, ah1, 0u, 0u, bh0, 0u);   // hi*hi
            mma_bf16(acc[j], ah0, ah1, 0u, 0u, bl0, 0u);   // hi*lo
            mma_bf16(acc[j], al0, al1, 0u, 0u, bh0, 0u);   // lo*hi
        }
    }

    const float bv0 = bsm[row],     ob0 = 1.f - bv0;
    const float bv1 = bsm[row + 8], ob1 = 1.f - bv1;
    #pragma unroll
    for (int j = 0; j < 8; j++) {
        int col = hc + nh*64 + j*8 + 2*tg;
        size_t base0 = ((size_t)b * T_ + row)     * H_ + col;
        size_t base1 = ((size_t)b * T_ + row + 8) * H_ + col;
        float2 s0 = *(const float2*)&s_t[base0];
        float2 s1 = *(const float2*)&s_t[base1];
        float2 o0, o1;
        o0.x = fmaf(bv0, s0.x, ob0 * acc[j][0]);
        o0.y = fmaf(bv0, s0.y, ob0 * acc[j][1]);
        o1.x = fmaf(bv1, s1.x, ob1 * acc[j][2]);
        o1.y = fmaf(bv1, s1.y, ob1 * acc[j][3]);
        *(float2*)&out[base0] = o0;
        *(float2*)&out[base1] = o1;
    }
}

// ---------------------------------------------------------------------------
// Host launch with PDL (programmatic stream serialization) on consumers.
// ---------------------------------------------------------------------------
static void launch_pdl(const void* func, dim3 grid, dim3 block, size_t smem,
                       void** args)
{
    cudaLaunchConfig_t cfg = {};
    cfg.gridDim = grid;
    cfg.blockDim = block;
    cfg.dynamicSmemBytes = smem;
    cudaLaunchAttribute attr[1];
    attr[0].id = cudaLaunchAttributeProgrammaticStreamSerialization;
    attr[0].val.programmaticStreamSerializationAllowed = 1;
    cfg.attrs = attr;
    cfg.numAttrs = 1;
    cudaLaunchKernelExC(&cfg, func, args);
}

extern "C" void kernel_launch(void* const* d_in, const int* in_sizes, int n_in,
                              void* d_out, int out_size)
{
    (void)in_sizes; (void)n_in; (void)out_size;
    const float* V   = (const float*)d_in[0];   // (B,K,H)
    const float* h_t = (const float*)d_in[1];   // (B,T,H)
    const float* s_t = (const float*)d_in[2];   // (B,T,H)
    const float* Wv  = (const float*)d_in[3];   // (K,H)
    const float* Wg  = (const float*)d_in[4];   // (K,H)
    const float* Ws_ = (const float*)d_in[5];   // (K,H)
    const float* Wh  = (const float*)d_in[6];   // (1,K)

    float* out       = (float*)d_out;
    float* out_chat  = out;                 // (B,T,H)
    float* out_alpha = out + BTH;           // (B,T,K)
    float* out_beta  = out + BTH + BTK;     // (B,T,1)

    cudaFuncSetAttribute(chat_mma_kernel,
                         cudaFuncAttributeMaxDynamicSharedMemorySize, SMEM_CHAT);

    wperm_kernel<<<192, 128>>>(Wv, Wg, Ws_);

    {
        void* args[] = { (void*)&V, (void*)&h_t, (void*)&s_t };
        launch_pdl((const void*)gemm_mma_kernel, dim3(708), dim3(128), 0, args);
    }
    {
        void* args[] = { (void*)&Wh, (void*)&out_alpha, (void*)&out_beta };
        launch_pdl((const void*)zsoft_kernel, dim3(4, B_), dim3(256), 0, args);
    }
    {
        void* args[] = { (void*)&V, (void*)&s_t, (void*)&out_beta, (void*)&out_chat };
        launch_pdl((const void*)chat_mma_kernel, dim3(4, B_), dim3(256), SMEM_CHAT, args);
    }
}